// round 4
// baseline (speedup 1.0000x reference)
#include <cuda_runtime.h>
#include <cstdint>
#include <cstddef>

// ============================================================================
// Shapes (fixed by setup_inputs)
// ============================================================================
#define TOK   16384      // B*S
#define DIM   2048
#define HID   8192

// GEMM tiling: BM=128, BN=128, BK=64 int8-bytes, 8 warps (2m x 4n), 4 stages
#define STAGE_BYTES 16384          // A 128*64 + B 128*64
#define STG 4
#define SMEM_TOTAL (STG * STAGE_BYTES)

#define S_H_INV (127.0f / 8.0f)    // h quant scale
#define S_H     (8.0f / 127.0f)

// ============================================================================
// Device scratch (allocation-free rule: __device__ globals)
// ============================================================================
__device__ __align__(16) signed char g_Wup8  [16777216];    // [HID, DIM] ternary int8
__device__ __align__(16) signed char g_Wdown8[16777216];    // [DIM, HID] ternary int8
__device__ __align__(16) signed char g_Xq8   [33554432];    // [TOK, DIM] act int8
__device__ __align__(16) signed char g_Hq    [134217728];   // [TOK, HID] silu(h) int8
__device__ float g_sx[TOK];
__device__ float g_scaleinfo[4];   // s_up, 1/s_up, s_down, 1/s_down
__device__ float g_part[2048];

// ============================================================================
// Helpers
// ============================================================================
__device__ __forceinline__ uint32_t smem_to_u32(const void* p) {
    uint32_t a;
    asm("{ .reg .u64 t; cvta.to.shared.u64 t, %1; cvt.u32.u64 %0, t; }"
        : "=r"(a) : "l"(p));
    return a;
}

__device__ __forceinline__ void cp_async16(uint32_t dst_smem, const void* src) {
    asm volatile("cp.async.cg.shared.global [%0], [%1], 16;"
                 :: "r"(dst_smem), "l"(src));
}
#define CP_COMMIT() asm volatile("cp.async.commit_group;" ::: "memory")
#define CP_WAIT_0() asm volatile("cp.async.wait_group 0;" ::: "memory")
#define CP_WAIT_1() asm volatile("cp.async.wait_group 1;" ::: "memory")
#define CP_WAIT_2() asm volatile("cp.async.wait_group 2;" ::: "memory")

__device__ __forceinline__ uint32_t lds32(uint32_t a) {
    uint32_t v;
    asm volatile("ld.shared.b32 %0, [%1];" : "=r"(v) : "r"(a));
    return v;
}

// int8 IMMA: D[16x8] s32 += A[16x32] s8 * B[32x8] s8
__device__ __forceinline__ void mma_s8(int* d, const uint32_t* a, const uint32_t* b) {
    asm volatile(
        "mma.sync.aligned.m16n8k32.row.col.s32.s8.s8.s32 "
        "{%0,%1,%2,%3}, {%4,%5,%6,%7}, {%8,%9}, {%0,%1,%2,%3};"
        : "+r"(d[0]), "+r"(d[1]), "+r"(d[2]), "+r"(d[3])
        : "r"(a[0]), "r"(a[1]), "r"(a[2]), "r"(a[3]), "r"(b[0]), "r"(b[1]));
}

// Swizzled smem offset for a [128 rows x 64 bytes] tile stored as 64 phases of
// 128B (two rows per phase), 16B chunks XOR-rotated by (phase & 7).
// Conflict-free for both cp.async 16B writes and per-fragment 4B reads
// (fragment phases are 4/8-aligned so even/odd-row chunks can't alias).
__device__ __forceinline__ uint32_t sw_off(int row, int byte) {
    uint32_t phase = (uint32_t)row >> 1;
    uint32_t chunk = (uint32_t)(((row & 1) << 2) | (byte >> 4)) ^ (phase & 7u);
    return phase * 128u + chunk * 16u + ((uint32_t)byte & 15u);
}

__device__ __forceinline__ int pack4(float q0, float q1, float q2, float q3) {
    int b0 = __float2int_rn(q0) & 0xff;
    int b1 = __float2int_rn(q1) & 0xff;
    int b2 = __float2int_rn(q2) & 0xff;
    int b3 = __float2int_rn(q3) & 0xff;
    return b0 | (b1 << 8) | (b2 << 16) | (b3 << 24);
}

// ============================================================================
// Prep 1: partial abs-sums of both weight matrices (deterministic tree)
// ============================================================================
__global__ void __launch_bounds__(256) k_abs_part(const float* __restrict__ wu,
                                                  const float* __restrict__ wd) {
    __shared__ float red[8];
    int b = blockIdx.x;
    const float* w = (b < 1024) ? wu : wd;
    size_t base = (size_t)((b < 1024) ? b : b - 1024) * 16384;
    const float4* p = (const float4*)(w + base);
    float s = 0.f;
    for (int j = threadIdx.x; j < 4096; j += 256) {
        float4 v = p[j];
        s += fabsf(v.x) + fabsf(v.y) + fabsf(v.z) + fabsf(v.w);
    }
    int wid = threadIdx.x >> 5, l = threadIdx.x & 31;
    for (int o = 16; o; o >>= 1) s += __shfl_xor_sync(0xFFFFFFFFu, s, o);
    if (!l) red[wid] = s;
    __syncthreads();
    if (threadIdx.x == 0) {
        float t = 0.f;
        for (int k = 0; k < 8; k++) t += red[k];
        g_part[b] = t;
    }
}

// Prep 2: finalize scales
__global__ void __launch_bounds__(1024) k_abs_fin() {
    __shared__ float su[32], sdn[32];
    int t = threadIdx.x, w = t >> 5, l = t & 31;
    float a = g_part[t];
    float b = g_part[1024 + t];
    for (int o = 16; o; o >>= 1) {
        a += __shfl_xor_sync(0xFFFFFFFFu, a, o);
        b += __shfl_xor_sync(0xFFFFFFFFu, b, o);
    }
    if (!l) { su[w] = a; sdn[w] = b; }
    __syncthreads();
    if (!w) {
        a = su[l]; b = sdn[l];
        for (int o = 16; o; o >>= 1) {
            a += __shfl_xor_sync(0xFFFFFFFFu, a, o);
            b += __shfl_xor_sync(0xFFFFFFFFu, b, o);
        }
        if (!l) {
            float m1 = a * (1.0f / 16777216.0f);
            float m2 = b * (1.0f / 16777216.0f);
            float s1 = fmaxf(m1, 1e-8f), s2 = fmaxf(m2, 1e-8f);
            g_scaleinfo[0] = s1; g_scaleinfo[1] = 1.0f / s1;
            g_scaleinfo[2] = s2; g_scaleinfo[3] = 1.0f / s2;
        }
    }
}

// Prep 3: ternary-quantize both weights to int8 {-1,0,1}
__global__ void __launch_bounds__(256) k_quant(const float* __restrict__ wu,
                                               const float* __restrict__ wd) {
    int b = blockIdx.x;
    const float* src; signed char* dst; float inv; size_t base;
    if (b < 16384) { src = wu; dst = g_Wup8;   inv = g_scaleinfo[1]; base = (size_t)b * 1024; }
    else           { src = wd; dst = g_Wdown8; inv = g_scaleinfo[3]; base = (size_t)(b - 16384) * 1024; }
    size_t i = base + (size_t)threadIdx.x * 4u;
    float4 v = *(const float4*)(src + i);
    float q0 = fminf(fmaxf(rintf(v.x * inv), -1.f), 1.f);
    float q1 = fminf(fmaxf(rintf(v.y * inv), -1.f), 1.f);
    float q2 = fminf(fmaxf(rintf(v.z * inv), -1.f), 1.f);
    float q3 = fminf(fmaxf(rintf(v.w * inv), -1.f), 1.f);
    *(int*)(dst + i) = pack4(q0, q1, q2, q3);
}

// Prep 4: fused rmsnorm + per-token int8 activation quant
__global__ void __launch_bounds__(256) k_act(const float* __restrict__ x,
                                             const float* __restrict__ nw) {
    __shared__ float red[8];
    __shared__ float bc;
    int t = blockIdx.x, tid = threadIdx.x, w = tid >> 5, l = tid & 31;
    const float4* xp = (const float4*)(x + (size_t)t * 2048);
    const float4* np = (const float4*)nw;
    float4 a = xp[tid], b = xp[tid + 256];
    float ss = a.x*a.x + a.y*a.y + a.z*a.z + a.w*a.w
             + b.x*b.x + b.y*b.y + b.z*b.z + b.w*b.w;
    for (int o = 16; o; o >>= 1) ss += __shfl_xor_sync(0xFFFFFFFFu, ss, o);
    if (!l) red[w] = ss;
    __syncthreads();
    if (tid == 0) {
        float v = 0.f;
        for (int k = 0; k < 8; k++) v += red[k];
        bc = v;
    }
    __syncthreads();
    float mean = bc * (1.0f / 2048.0f) + 1e-6f;
    float r = rsqrtf(mean);
    r = r * (1.5f - 0.5f * mean * r * r);   // Newton refine to fp32 accuracy
    float4 na = np[tid], nb = np[tid + 256];
    float xn[8] = { a.x*r*na.x, a.y*r*na.y, a.z*r*na.z, a.w*r*na.w,
                    b.x*r*nb.x, b.y*r*nb.y, b.z*r*nb.z, b.w*r*nb.w };
    float mx = 0.f;
    #pragma unroll
    for (int k = 0; k < 8; k++) mx = fmaxf(mx, fabsf(xn[k]));
    for (int o = 16; o; o >>= 1) mx = fmaxf(mx, __shfl_xor_sync(0xFFFFFFFFu, mx, o));
    __syncthreads();
    if (!l) red[w] = mx;
    __syncthreads();
    if (tid == 0) {
        float v = 0.f;
        for (int k = 0; k < 8; k++) v = fmaxf(v, red[k]);
        bc = fmaxf(v, 1e-8f);
    }
    __syncthreads();
    float g = bc;
    float inv = 127.0f / g;
    float q[8];
    #pragma unroll
    for (int k = 0; k < 8; k++)
        q[k] = fminf(fmaxf(rintf(xn[k] * inv), -127.f), 127.f);
    signed char* dst = g_Xq8 + (size_t)t * 2048;
    *(int*)(dst + tid * 4)        = pack4(q[0], q[1], q[2], q[3]);
    *(int*)(dst + 1024 + tid * 4) = pack4(q[4], q[5], q[6], q[7]);
    if (tid == 0) g_sx[t] = g * (1.0f / 127.0f);
}

// ============================================================================
// int8 IMMA GEMM: C[128,128] s32 = A[m0:,K] * B[n0:,K]^T (both K-major int8)
// EPI=1: h = silu(C * s_x * s_up); g_Hq = clamp(round(h*127/8))
// EPI=2: out = x + C * (8/127) * s_down * gamma
// ============================================================================
template<int EPI, int KD, int NT>
__global__ void __launch_bounds__(256, 1) gemm_kernel(const float* __restrict__ xres,
                                                      const float* __restrict__ gam,
                                                      float* __restrict__ outp) {
    extern __shared__ char smem[];
    const uint32_t sb = smem_to_u32(smem);
    const int tid  = threadIdx.x;
    const int wid  = tid >> 5, lane = tid & 31;
    const int g    = lane >> 2, tg = lane & 3;
    const int warp_m = wid >> 2;          // 0..1 -> m offset 64*warp_m
    const int warp_n = wid & 3;           // 0..3 -> n offset 32*warp_n
    constexpr int NK = KD / 64;

    const int m0 = (int)(blockIdx.x / NT) * 128;
    const int n0 = (int)(blockIdx.x % NT) * 128;
    const signed char* A = (EPI == 1) ? g_Xq8  : g_Hq;
    const signed char* B = (EPI == 1) ? g_Wup8 : g_Wdown8;

    // --- copy plan: 1024 x 16B chunks per stage, 4 per thread ---
    const char* srcp[4];
    uint32_t dstoff[4];
    #pragma unroll
    for (int j = 0; j < 4; j++) {
        int cid = tid + j * 256;          // 0..1023
        int isB = cid >= 512;
        int c   = isB ? cid - 512 : cid;
        int row = c >> 2;
        int byt = (c & 3) * 16;
        const signed char* base = isB ? (B + (size_t)(n0 + row) * KD)
                                      : (A + (size_t)(m0 + row) * KD);
        srcp[j]   = (const char*)base + byt;
        dstoff[j] = (isB ? 8192u : 0u) + sw_off(row, byt);
    }
    auto do_load = [&](int kt) {
        uint32_t sbase = sb + (uint32_t)(kt & 3) * STAGE_BYTES;
        size_t ko = (size_t)kt * 64;
        #pragma unroll
        for (int j = 0; j < 4; j++) cp_async16(sbase + dstoff[j], srcp[j] + ko);
        CP_COMMIT();
    };

    do_load(0); do_load(1); do_load(2);

    int acc[4][4][4];
    #pragma unroll
    for (int i = 0; i < 4; i++)
        #pragma unroll
        for (int j = 0; j < 4; j++)
            #pragma unroll
            for (int k = 0; k < 4; k++) acc[i][j][k] = 0;

    for (int kt = 0; kt < NK; kt++) {
        if (kt + 2 < NK)      { CP_WAIT_2(); }
        else if (kt + 1 < NK) { CP_WAIT_1(); }
        else                  { CP_WAIT_0(); }
        __syncthreads();
        if (kt + 3 < NK) do_load(kt + 3);   // refill slot consumed last iter

        uint32_t sa  = sb + (uint32_t)(kt & 3) * STAGE_BYTES;
        uint32_t sbb = sa + 8192;
        #pragma unroll
        for (int kc = 0; kc < 2; kc++) {
            uint32_t a[4][4], b[4][2];
            #pragma unroll
            for (int mi = 0; mi < 4; mi++) {
                int r0 = warp_m * 64 + mi * 16 + g;
                int by = kc * 32 + tg * 4;
                a[mi][0] = lds32(sa + sw_off(r0,     by));
                a[mi][1] = lds32(sa + sw_off(r0 + 8, by));
                a[mi][2] = lds32(sa + sw_off(r0,     by + 16));
                a[mi][3] = lds32(sa + sw_off(r0 + 8, by + 16));
            }
            #pragma unroll
            for (int ni = 0; ni < 4; ni++) {
                int rn = warp_n * 32 + ni * 8 + g;
                int by = kc * 32 + tg * 4;
                b[ni][0] = lds32(sbb + sw_off(rn, by));
                b[ni][1] = lds32(sbb + sw_off(rn, by + 16));
            }
            #pragma unroll
            for (int mi = 0; mi < 4; mi++)
                #pragma unroll
                for (int ni = 0; ni < 4; ni++)
                    mma_s8(acc[mi][ni], a[mi], b[ni]);
        }
        __syncthreads();
    }

    // ---- epilogue ----
    if (EPI == 1) {
        float sup = g_scaleinfo[0];
        #pragma unroll
        for (int mi = 0; mi < 4; mi++) {
            int r0 = m0 + warp_m * 64 + mi * 16 + g;
            float sc0 = g_sx[r0]     * sup;
            float sc1 = g_sx[r0 + 8] * sup;
            #pragma unroll
            for (int ni = 0; ni < 4; ni++) {
                int col = n0 + warp_n * 32 + ni * 8 + 2 * tg;
                float v0 = (float)acc[mi][ni][0] * sc0;
                float v1 = (float)acc[mi][ni][1] * sc0;
                float v2 = (float)acc[mi][ni][2] * sc1;
                float v3 = (float)acc[mi][ni][3] * sc1;
                v0 = v0 / (1.0f + __expf(-v0));
                v1 = v1 / (1.0f + __expf(-v1));
                v2 = v2 / (1.0f + __expf(-v2));
                v3 = v3 / (1.0f + __expf(-v3));
                int q01 = (__float2int_rn(fminf(fmaxf(v0 * S_H_INV, -127.f), 127.f)) & 0xff)
                        | ((__float2int_rn(fminf(fmaxf(v1 * S_H_INV, -127.f), 127.f)) & 0xff) << 8);
                int q23 = (__float2int_rn(fminf(fmaxf(v2 * S_H_INV, -127.f), 127.f)) & 0xff)
                        | ((__float2int_rn(fminf(fmaxf(v3 * S_H_INV, -127.f), 127.f)) & 0xff) << 8);
                *(short*)(g_Hq + (size_t)r0       * HID + col) = (short)q01;
                *(short*)(g_Hq + (size_t)(r0 + 8) * HID + col) = (short)q23;
            }
        }
    } else {
        float sd = g_scaleinfo[2] * S_H;
        #pragma unroll
        for (int mi = 0; mi < 4; mi++) {
            int r0 = m0 + warp_m * 64 + mi * 16 + g;
            #pragma unroll
            for (int ni = 0; ni < 4; ni++) {
                int col = n0 + warp_n * 32 + ni * 8 + 2 * tg;
                float g0 = __ldg(gam + col) * sd;
                float g1 = __ldg(gam + col + 1) * sd;
                const float* x0 = xres + (size_t)r0 * DIM + col;
                const float* x1 = xres + (size_t)(r0 + 8) * DIM + col;
                float* o0 = outp + (size_t)r0 * DIM + col;
                float* o1 = outp + (size_t)(r0 + 8) * DIM + col;
                o0[0] = x0[0] + (float)acc[mi][ni][0] * g0;
                o0[1] = x0[1] + (float)acc[mi][ni][1] * g1;
                o1[0] = x1[0] + (float)acc[mi][ni][2] * g0;
                o1[1] = x1[1] + (float)acc[mi][ni][3] * g1;
            }
        }
    }
}

// ============================================================================
// Launch
// ============================================================================
extern "C" void kernel_launch(void* const* d_in, const int* in_sizes, int n_in,
                              void* d_out, int out_size) {
    const float* x  = (const float*)d_in[0];
    const float* wu = (const float*)d_in[1];
    const float* wd = (const float*)d_in[2];
    const float* nw = (const float*)d_in[3];
    const float* gm = (const float*)d_in[4];
    float* out = (float*)d_out;

    cudaFuncSetAttribute(gemm_kernel<1, DIM, 64>,
                         cudaFuncAttributeMaxDynamicSharedMemorySize, SMEM_TOTAL);
    cudaFuncSetAttribute(gemm_kernel<2, HID, 16>,
                         cudaFuncAttributeMaxDynamicSharedMemorySize, SMEM_TOTAL);

    k_abs_part<<<2048, 256>>>(wu, wd);
    k_abs_fin<<<1, 1024>>>();
    k_quant<<<32768, 256>>>(wu, wd);
    k_act<<<16384, 256>>>(x, nw);
    // GEMM1: M=16384, N=8192, K=2048 -> 128 x 64 tiles, n-fast (weights L2-resident)
    gemm_kernel<1, DIM, 64><<<8192, 256, SMEM_TOTAL>>>(nullptr, nullptr, nullptr);
    // GEMM2: M=16384, N=2048, K=8192 -> 128 x 16 tiles, n-fast
    gemm_kernel<2, HID, 16><<<2048, 256, SMEM_TOTAL>>>(x, gm, out);
}

// round 7
// speedup vs baseline: 1.5392x; 1.5392x over previous
#include <cuda_runtime.h>
#include <cstdint>
#include <cstddef>

// ============================================================================
// Shapes (fixed by setup_inputs)
// ============================================================================
#define TOK   16384      // B*S
#define DIM   2048
#define HID   8192

// GEMM tiling: BM=128, BN=128, BK=64 int8-bytes, 8 warps (2m x 4n), 4 stages
#define STAGE_BYTES 16384          // A 128*64 + B 128*64
#define STG 4
#define SMEM_TOTAL (STG * STAGE_BYTES)

#define S_H_INV (127.0f / 8.0f)    // h quant scale
#define S_H     (8.0f / 127.0f)

// ============================================================================
// Device scratch (allocation-free rule: __device__ globals)
// ============================================================================
__device__ __align__(16) signed char g_Wup8  [16777216];    // [HID, DIM] ternary int8
__device__ __align__(16) signed char g_Wdown8[16777216];    // [DIM, HID] ternary int8
__device__ __align__(16) signed char g_Xq8   [33554432];    // [TOK, DIM] act int8
__device__ __align__(16) signed char g_Hq    [134217728];   // [TOK, HID] silu(h) int8
__device__ float g_sx[TOK];
__device__ float g_scaleinfo[4];   // s_up, 1/s_up, s_down, 1/s_down
__device__ float g_part[2048];
__device__ unsigned int g_ctr = 0;

// ============================================================================
// Helpers
// ============================================================================
__device__ __forceinline__ uint32_t smem_to_u32(const void* p) {
    uint32_t a;
    asm("{ .reg .u64 t; cvta.to.shared.u64 t, %1; cvt.u32.u64 %0, t; }"
        : "=r"(a) : "l"(p));
    return a;
}

__device__ __forceinline__ void cp_async16(uint32_t dst_smem, const void* src) {
    asm volatile("cp.async.cg.shared.global [%0], [%1], 16;"
                 :: "r"(dst_smem), "l"(src));
}
#define CP_COMMIT() asm volatile("cp.async.commit_group;" ::: "memory")
#define CP_WAIT_0() asm volatile("cp.async.wait_group 0;" ::: "memory")
#define CP_WAIT_1() asm volatile("cp.async.wait_group 1;" ::: "memory")
#define CP_WAIT_2() asm volatile("cp.async.wait_group 2;" ::: "memory")

// ldmatrix x4: 4 matrices of 8 rows x 16B; lane L supplies the row address for
// matrix L/8, row L%8. Reg j <- matrix j; thread t holds bytes 4*(t%4).. of
// row t/4 (exactly the IMMA s8 fragment layout).
__device__ __forceinline__ void ldsm_x4(uint32_t* r, uint32_t addr) {
    asm volatile("ldmatrix.sync.aligned.m8n8.x4.shared.b16 {%0,%1,%2,%3}, [%4];"
                 : "=r"(r[0]), "=r"(r[1]), "=r"(r[2]), "=r"(r[3]) : "r"(addr));
}

// int8 IMMA: D[16x8] s32 += A[16x32] s8 * B[32x8] s8
__device__ __forceinline__ void mma_s8(int* d, const uint32_t* a, const uint32_t* b) {
    asm volatile(
        "mma.sync.aligned.m16n8k32.row.col.s32.s8.s8.s32 "
        "{%0,%1,%2,%3}, {%4,%5,%6,%7}, {%8,%9}, {%0,%1,%2,%3};"
        : "+r"(d[0]), "+r"(d[1]), "+r"(d[2]), "+r"(d[3])
        : "r"(a[0]), "r"(a[1]), "r"(a[2]), "r"(a[3]), "r"(b[0]), "r"(b[1]));
}

// Swizzled smem offset for a [128 rows x 64 bytes] tile stored as 64 phases of
// 128B (two rows per phase), 16B chunks XOR-rotated by (phase & 7).
// Conflict-free for cp.async 16B writes, LDSM 8-row gathers (all 8 chunk
// columns distinct per matrix), and +16 rows == +1024B (affine in tile index).
__device__ __forceinline__ uint32_t sw_off(int row, int byte) {
    uint32_t phase = (uint32_t)row >> 1;
    uint32_t chunk = (uint32_t)(((row & 1) << 2) | (byte >> 4)) ^ (phase & 7u);
    return phase * 128u + chunk * 16u + ((uint32_t)byte & 15u);
}

__device__ __forceinline__ int pack4(float q0, float q1, float q2, float q3) {
    int b0 = __float2int_rn(q0) & 0xff;
    int b1 = __float2int_rn(q1) & 0xff;
    int b2 = __float2int_rn(q2) & 0xff;
    int b3 = __float2int_rn(q3) & 0xff;
    return b0 | (b1 << 8) | (b2 << 16) | (b3 << 24);
}

// ============================================================================
// Prep 1: abs-mean scales for both weight matrices, single fused kernel
// (partial sums + last-block final reduction; deterministic sums)
// ============================================================================
__global__ void __launch_bounds__(256) k_scales(const float* __restrict__ wu,
                                                const float* __restrict__ wd) {
    __shared__ float red[8];
    __shared__ unsigned is_last;
    int b = blockIdx.x;
    const float* w = (b < 1024) ? wu : wd;
    size_t base = (size_t)((b < 1024) ? b : b - 1024) * 16384;
    const float4* p = (const float4*)(w + base);
    float s = 0.f;
    for (int j = threadIdx.x; j < 4096; j += 256) {
        float4 v = p[j];
        s += fabsf(v.x) + fabsf(v.y) + fabsf(v.z) + fabsf(v.w);
    }
    int wid = threadIdx.x >> 5, l = threadIdx.x & 31;
    for (int o = 16; o; o >>= 1) s += __shfl_xor_sync(0xFFFFFFFFu, s, o);
    if (!l) red[wid] = s;
    __syncthreads();
    if (threadIdx.x == 0) {
        float t = 0.f;
        for (int k = 0; k < 8; k++) t += red[k];
        g_part[b] = t;
        __threadfence();
        is_last = (atomicAdd(&g_ctr, 1u) == 2047u);
    }
    __syncthreads();
    if (is_last) {
        __threadfence();
        float a = 0.f, c = 0.f;
        for (int i = threadIdx.x; i < 1024; i += 256) {
            a += g_part[i];
            c += g_part[1024 + i];
        }
        __shared__ float ra[8], rc[8];
        for (int o = 16; o; o >>= 1) {
            a += __shfl_xor_sync(0xFFFFFFFFu, a, o);
            c += __shfl_xor_sync(0xFFFFFFFFu, c, o);
        }
        if (!l) { ra[wid] = a; rc[wid] = c; }
        __syncthreads();
        if (threadIdx.x == 0) {
            float ta = 0.f, tc = 0.f;
            for (int k = 0; k < 8; k++) { ta += ra[k]; tc += rc[k]; }
            float m1 = ta * (1.0f / 16777216.0f);
            float m2 = tc * (1.0f / 16777216.0f);
            float s1 = fmaxf(m1, 1e-8f), s2 = fmaxf(m2, 1e-8f);
            g_scaleinfo[0] = s1; g_scaleinfo[1] = 1.0f / s1;
            g_scaleinfo[2] = s2; g_scaleinfo[3] = 1.0f / s2;
            g_ctr = 0;   // reset for next graph replay
        }
    }
}

// Prep 2: ternary-quantize both weights to int8 {-1,0,1}
__global__ void __launch_bounds__(256) k_quant(const float* __restrict__ wu,
                                               const float* __restrict__ wd) {
    int b = blockIdx.x;
    const float* src; signed char* dst; float inv; size_t base;
    if (b < 16384) { src = wu; dst = g_Wup8;   inv = g_scaleinfo[1]; base = (size_t)b * 1024; }
    else           { src = wd; dst = g_Wdown8; inv = g_scaleinfo[3]; base = (size_t)(b - 16384) * 1024; }
    size_t i = base + (size_t)threadIdx.x * 4u;
    float4 v = *(const float4*)(src + i);
    float q0 = fminf(fmaxf(rintf(v.x * inv), -1.f), 1.f);
    float q1 = fminf(fmaxf(rintf(v.y * inv), -1.f), 1.f);
    float q2 = fminf(fmaxf(rintf(v.z * inv), -1.f), 1.f);
    float q3 = fminf(fmaxf(rintf(v.w * inv), -1.f), 1.f);
    *(int*)(dst + i) = pack4(q0, q1, q2, q3);
}

// Prep 3: fused rmsnorm + per-token int8 activation quant
__global__ void __launch_bounds__(256) k_act(const float* __restrict__ x,
                                             const float* __restrict__ nw) {
    __shared__ float red[8];
    __shared__ float bc;
    int t = blockIdx.x, tid = threadIdx.x, w = tid >> 5, l = tid & 31;
    const float4* xp = (const float4*)(x + (size_t)t * 2048);
    const float4* np = (const float4*)nw;
    float4 a = xp[tid], b = xp[tid + 256];
    float ss = a.x*a.x + a.y*a.y + a.z*a.z + a.w*a.w
             + b.x*b.x + b.y*b.y + b.z*b.z + b.w*b.w;
    for (int o = 16; o; o >>= 1) ss += __shfl_xor_sync(0xFFFFFFFFu, ss, o);
    if (!l) red[w] = ss;
    __syncthreads();
    if (tid == 0) {
        float v = 0.f;
        for (int k = 0; k < 8; k++) v += red[k];
        bc = v;
    }
    __syncthreads();
    float mean = bc * (1.0f / 2048.0f) + 1e-6f;
    float r = rsqrtf(mean);
    r = r * (1.5f - 0.5f * mean * r * r);   // Newton refine to fp32 accuracy
    float4 na = np[tid], nb = np[tid + 256];
    float xn[8] = { a.x*r*na.x, a.y*r*na.y, a.z*r*na.z, a.w*r*na.w,
                    b.x*r*nb.x, b.y*r*nb.y, b.z*r*nb.z, b.w*r*nb.w };
    float mx = 0.f;
    #pragma unroll
    for (int k = 0; k < 8; k++) mx = fmaxf(mx, fabsf(xn[k]));
    for (int o = 16; o; o >>= 1) mx = fmaxf(mx, __shfl_xor_sync(0xFFFFFFFFu, mx, o));
    __syncthreads();
    if (!l) red[w] = mx;
    __syncthreads();
    if (tid == 0) {
        float v = 0.f;
        for (int k = 0; k < 8; k++) v = fmaxf(v, red[k]);
        bc = fmaxf(v, 1e-8f);
    }
    __syncthreads();
    float g = bc;
    float inv = 127.0f / g;
    float q[8];
    #pragma unroll
    for (int k = 0; k < 8; k++)
        q[k] = fminf(fmaxf(rintf(xn[k] * inv), -127.f), 127.f);
    signed char* dst = g_Xq8 + (size_t)t * 2048;
    *(int*)(dst + tid * 4)        = pack4(q[0], q[1], q[2], q[3]);
    *(int*)(dst + 1024 + tid * 4) = pack4(q[4], q[5], q[6], q[7]);
    if (tid == 0) g_sx[t] = g * (1.0f / 127.0f);
}

// ============================================================================
// int8 IMMA GEMM: C[128,128] s32 = A[m0:,K] * B[n0:,K]^T (both K-major int8)
// ldmatrix fragment loads, 4-stage cp.async, one barrier per k-tile.
// EPI=1: h = silu(C * s_x * s_up); g_Hq = clamp(round(h*127/8))
// EPI=2: out = x + C * (8/127) * s_down * gamma
// ============================================================================
template<int EPI, int KD, int NT>
__global__ void __launch_bounds__(256, 2) gemm_kernel(const float* __restrict__ xres,
                                                      const float* __restrict__ gam,
                                                      float* __restrict__ outp) {
    extern __shared__ char smem[];
    const uint32_t sb = smem_to_u32(smem);
    const int tid  = threadIdx.x;
    const int wid  = tid >> 5, lane = tid & 31;
    const int g    = lane >> 2, tg = lane & 3;
    const int warp_m = wid >> 2;          // 0..1 -> m offset 64*warp_m
    const int warp_n = wid & 3;           // 0..3 -> n offset 32*warp_n
    constexpr int NK = KD / 64;

    const int m0 = (int)(blockIdx.x / NT) * 128;
    const int n0 = (int)(blockIdx.x % NT) * 128;
    const signed char* A = (EPI == 1) ? g_Xq8  : g_Hq;
    const signed char* B = (EPI == 1) ? g_Wup8 : g_Wdown8;

    // --- copy plan: 1024 x 16B chunks per stage, 4 per thread ---
    const char* srcp[4];
    uint32_t dstoff[4];
    #pragma unroll
    for (int j = 0; j < 4; j++) {
        int cid = tid + j * 256;          // 0..1023
        int isB = cid >= 512;
        int c   = isB ? cid - 512 : cid;
        int row = c >> 2;
        int byt = (c & 3) * 16;
        const signed char* base = isB ? (B + (size_t)(n0 + row) * KD)
                                      : (A + (size_t)(m0 + row) * KD);
        srcp[j]   = (const char*)base + byt;
        dstoff[j] = (isB ? 8192u : 0u) + sw_off(row, byt);
    }
    auto do_load = [&](int kt) {
        uint32_t sbase = sb + (uint32_t)(kt & 3) * STAGE_BYTES;
        size_t ko = (size_t)kt * 64;
        #pragma unroll
        for (int j = 0; j < 4; j++) cp_async16(sbase + dstoff[j], srcp[j] + ko);
        CP_COMMIT();
    };

    // --- ldmatrix per-lane address offsets (relative to stage base) ---
    const int sub = lane & 7, mat = lane >> 3;
    uint32_t offA[2], offB[2];
    #pragma unroll
    for (int kc = 0; kc < 2; kc++) {
        offA[kc] = sw_off(warp_m * 64 + sub + ((mat & 1) << 3),
                          kc * 32 + ((mat >> 1) << 4));
        offB[kc] = 8192u + sw_off(warp_n * 32 + sub + ((mat >> 1) << 3),
                                  kc * 32 + ((mat & 1) << 4));
    }

    do_load(0); do_load(1); do_load(2);

    int acc[4][4][4];
    #pragma unroll
    for (int i = 0; i < 4; i++)
        #pragma unroll
        for (int j = 0; j < 4; j++)
            #pragma unroll
            for (int k = 0; k < 4; k++) acc[i][j][k] = 0;

    for (int kt = 0; kt < NK; kt++) {
        if (kt + 2 < NK)      { CP_WAIT_2(); }
        else if (kt + 1 < NK) { CP_WAIT_1(); }
        else                  { CP_WAIT_0(); }
        __syncthreads();               // single barrier per k-tile
        if (kt + 3 < NK) do_load(kt + 3);   // refill slot consumed at kt-1

        uint32_t sa = sb + (uint32_t)(kt & 3) * STAGE_BYTES;
        #pragma unroll
        for (int kc = 0; kc < 2; kc++) {
            uint32_t af[4][4], bf[2][4];
            #pragma unroll
            for (int mi = 0; mi < 4; mi++)
                ldsm_x4(af[mi], sa + offA[kc] + (uint32_t)mi * 1024u);
            #pragma unroll
            for (int p = 0; p < 2; p++)
                ldsm_x4(bf[p], sa + offB[kc] + (uint32_t)p * 1024u);
            #pragma unroll
            for (int mi = 0; mi < 4; mi++)
                #pragma unroll
                for (int ni = 0; ni < 4; ni++)
                    mma_s8(acc[mi][ni], af[mi], &bf[ni >> 1][(ni & 1) * 2]);
        }
    }

    // ---- epilogue ----
    if (EPI == 1) {
        float sup = g_scaleinfo[0];
        #pragma unroll
        for (int mi = 0; mi < 4; mi++) {
            int r0 = m0 + warp_m * 64 + mi * 16 + g;
            float sc0 = g_sx[r0]     * sup;
            float sc1 = g_sx[r0 + 8] * sup;
            #pragma unroll
            for (int ni = 0; ni < 4; ni++) {
                int col = n0 + warp_n * 32 + ni * 8 + 2 * tg;
                float v0 = (float)acc[mi][ni][0] * sc0;
                float v1 = (float)acc[mi][ni][1] * sc0;
                float v2 = (float)acc[mi][ni][2] * sc1;
                float v3 = (float)acc[mi][ni][3] * sc1;
                v0 = v0 / (1.0f + __expf(-v0));
                v1 = v1 / (1.0f + __expf(-v1));
                v2 = v2 / (1.0f + __expf(-v2));
                v3 = v3 / (1.0f + __expf(-v3));
                int q01 = (__float2int_rn(fminf(fmaxf(v0 * S_H_INV, -127.f), 127.f)) & 0xff)
                        | ((__float2int_rn(fminf(fmaxf(v1 * S_H_INV, -127.f), 127.f)) & 0xff) << 8);
                int q23 = (__float2int_rn(fminf(fmaxf(v2 * S_H_INV, -127.f), 127.f)) & 0xff)
                        | ((__float2int_rn(fminf(fmaxf(v3 * S_H_INV, -127.f), 127.f)) & 0xff) << 8);
                *(short*)(g_Hq + (size_t)r0       * HID + col) = (short)q01;
                *(short*)(g_Hq + (size_t)(r0 + 8) * HID + col) = (short)q23;
            }
        }
    } else {
        float sd = g_scaleinfo[2] * S_H;
        #pragma unroll
        for (int mi = 0; mi < 4; mi++) {
            int r0 = m0 + warp_m * 64 + mi * 16 + g;
            #pragma unroll
            for (int ni = 0; ni < 4; ni++) {
                int col = n0 + warp_n * 32 + ni * 8 + 2 * tg;
                float g0 = __ldg(gam + col) * sd;
                float g1 = __ldg(gam + col + 1) * sd;
                const float* x0 = xres + (size_t)r0 * DIM + col;
                const float* x1 = xres + (size_t)(r0 + 8) * DIM + col;
                float* o0 = outp + (size_t)r0 * DIM + col;
                float* o1 = outp + (size_t)(r0 + 8) * DIM + col;
                o0[0] = x0[0] + (float)acc[mi][ni][0] * g0;
                o0[1] = x0[1] + (float)acc[mi][ni][1] * g1;
                o1[0] = x1[0] + (float)acc[mi][ni][2] * g0;
                o1[1] = x1[1] + (float)acc[mi][ni][3] * g1;
            }
        }
    }
}

// ============================================================================
// Launch
// ============================================================================
extern "C" void kernel_launch(void* const* d_in, const int* in_sizes, int n_in,
                              void* d_out, int out_size) {
    const float* x  = (const float*)d_in[0];
    const float* wu = (const float*)d_in[1];
    const float* wd = (const float*)d_in[2];
    const float* nw = (const float*)d_in[3];
    const float* gm = (const float*)d_in[4];
    float* out = (float*)d_out;

    cudaFuncSetAttribute(gemm_kernel<1, DIM, 64>,
                         cudaFuncAttributeMaxDynamicSharedMemorySize, SMEM_TOTAL);
    cudaFuncSetAttribute(gemm_kernel<2, HID, 16>,
                         cudaFuncAttributeMaxDynamicSharedMemorySize, SMEM_TOTAL);

    k_scales<<<2048, 256>>>(wu, wd);
    k_quant<<<32768, 256>>>(wu, wd);
    k_act<<<16384, 256>>>(x, nw);
    // GEMM1: M=16384, N=8192, K=2048 -> 128 x 64 tiles, n-fast (weights L2-resident)
    gemm_kernel<1, DIM, 64><<<8192, 256, SMEM_TOTAL>>>(nullptr, nullptr, nullptr);
    // GEMM2: M=16384, N=2048, K=8192 -> 128 x 16 tiles, n-fast
    gemm_kernel<2, HID, 16><<<2048, 256, SMEM_TOTAL>>>(x, gm, out);
}